// round 10
// baseline (speedup 1.0000x reference)
#include <cuda_runtime.h>
#include <cstdint>

// AUGRU: B=65536, T=50, E=10.
// Fold: (x@Wi + bi + h@Wh)@Ws + bs == x@(Wi@Ws) + h@(Wh@Ws) + (bi@Ws + bs)
// R10: split-E. Lanes L and L^16 co-own the same 2 batch elements; half-warp
// group grp=L>>4 owns gate outputs j in [5*grp, 5*grp+5). Each thread does half
// the dots for its 2 elements -> warps double to 2048 (3.46/SMSP) at constant
// per-element load/FMA cost. h and hz halves exchanged via shfl.xor(16) each
// step. Feature-packed f32x2 dots, const/smem weight-port split, tanh.approx,
// double-buffered cp.async staging.

#define E_  10
#define T_  50
#define B_  65536
#define NB  32           // threads per block
#define EB  32           // batch elems per block (2 per lane-pair)
#define RS  10           // floats per row per timestep
#define ROWB (T_*E_)     // 500 floats per batch row

// g_w2 layout (transposed A^T[j][k], row stride 12, 16B-aligned rows):
//   const part: Axr@0, Axz@120, Axh@240, biases br@360 bz@370 bh@380
//   smem part:  Ahr@400, Ahz@520, Ahh@640   (also stride 12)
__device__ float g_w2[880];

// constant mirror of g_w2[0..389]
__constant__ float c_w[390];

__global__ void augru_precompute(
    const float* __restrict__ Wi_r, const float* __restrict__ bi_r,
    const float* __restrict__ Wh_r, const float* __restrict__ Ws_r, const float* __restrict__ bs_r,
    const float* __restrict__ Wi_z, const float* __restrict__ bi_z,
    const float* __restrict__ Wh_z, const float* __restrict__ Ws_z, const float* __restrict__ bs_z,
    const float* __restrict__ Wi_h, const float* __restrict__ bi_h,
    const float* __restrict__ Wh_h, const float* __restrict__ Wt_h, const float* __restrict__ bt_h)
{
    int tid = threadIdx.x;
    if (tid < 600) {
        int m = tid / 100, rem = tid % 100, j = rem / 10, k = rem % 10;
        const float* W1; const float* W2; int dst;
        switch (m) {
            case 0: W1 = Wi_r; W2 = Ws_r; dst = 0;   break;  // Axr (const)
            case 1: W1 = Wh_r; W2 = Ws_r; dst = 400; break;  // Ahr (smem)
            case 2: W1 = Wi_z; W2 = Ws_z; dst = 120; break;  // Axz (const)
            case 3: W1 = Wh_z; W2 = Ws_z; dst = 520; break;  // Ahz (smem)
            case 4: W1 = Wi_h; W2 = Wt_h; dst = 240; break;  // Axh (const)
            default: W1 = Wh_h; W2 = Wt_h; dst = 640; break; // Ahh (smem)
        }
        float acc = 0.f;
        #pragma unroll
        for (int mm = 0; mm < E_; mm++)
            acc += W1[k * E_ + mm] * W2[mm * E_ + j];
        g_w2[dst + j * 12 + k] = acc;
    } else if (tid < 630) {
        int g = (tid - 600) / 10, j = (tid - 600) % 10;
        const float* bi; const float* Ws; const float* bs;
        if (g == 0)      { bi = bi_r; Ws = Ws_r; bs = bs_r; }
        else if (g == 1) { bi = bi_z; Ws = Ws_z; bs = bs_z; }
        else             { bi = bi_h; Ws = Wt_h; bs = bt_h; }
        float acc = bs[j];
        #pragma unroll
        for (int mm = 0; mm < E_; mm++)
            acc += bi[mm] * Ws[mm * E_ + j];
        g_w2[360 + g * 10 + j] = acc;
    }
}

__device__ __forceinline__ float2 fma2(float2 a, float2 b, float2 c) {
    unsigned long long ua = *reinterpret_cast<unsigned long long*>(&a);
    unsigned long long ub = *reinterpret_cast<unsigned long long*>(&b);
    unsigned long long uc = *reinterpret_cast<unsigned long long*>(&c);
    unsigned long long ud;
    asm("fma.rn.f32x2 %0, %1, %2, %3;" : "=l"(ud) : "l"(ua), "l"(ub), "l"(uc));
    return *reinterpret_cast<float2*>(&ud);
}

__device__ __forceinline__ float tanh_ap(float x) {
    float y;
    asm("tanh.approx.f32 %0, %1;" : "=f"(y) : "f"(x));
    return y;
}
__device__ __forceinline__ float sigf(float x) {
    return fmaf(0.5f, tanh_ap(0.5f * x), 0.5f);
}

// one 10-float weight row, loaded once (f4,f4,f2)
struct W10 { float4 a; float4 b; float2 c; };

__device__ __forceinline__ W10 ldrow(const float* __restrict__ w) {
    W10 r;
    r.a = *reinterpret_cast<const float4*>(w);
    r.b = *reinterpret_cast<const float4*>(w + 4);
    r.c = *reinterpret_cast<const float2*>(w + 8);
    return r;
}

// dot of loaded row with feature-packed vector v[5] into (even,odd) acc
__device__ __forceinline__ float2 dotw(const W10& w, const float2* __restrict__ v, float2 acc) {
    acc = fma2(make_float2(w.a.x, w.a.y), v[0], acc);
    acc = fma2(make_float2(w.a.z, w.a.w), v[1], acc);
    acc = fma2(make_float2(w.b.x, w.b.y), v[2], acc);
    acc = fma2(make_float2(w.b.z, w.b.w), v[3], acc);
    acc = fma2(w.c,                       v[4], acc);
    return acc;
}

// exchange 5 owned scalars with partner lane (xor 16) and build the full
// 10-feature packed vector: features [0..4] from grp0's array, [5..9] from grp1's.
__device__ __forceinline__ void exch5(const float* __restrict__ own, bool is0,
                                      float2* __restrict__ packed) {
    float rec[5];
    #pragma unroll
    for (int k = 0; k < 5; k++)
        rec[k] = __shfl_xor_sync(0xffffffffu, own[k], 16);
    float f[10];
    #pragma unroll
    for (int k = 0; k < 5; k++) {
        f[k]     = is0 ? own[k] : rec[k];
        f[5 + k] = is0 ? rec[k] : own[k];
    }
    #pragma unroll
    for (int i = 0; i < 5; i++)
        packed[i] = make_float2(f[2 * i], f[2 * i + 1]);
}

__device__ __forceinline__ void cpa8(uint32_t smem_addr, const void* gptr) {
    asm volatile("cp.async.ca.shared.global [%0], [%1], 8;" :: "r"(smem_addr), "l"(gptr));
}

__global__ void __launch_bounds__(NB, 14) augru_main(
    const float* __restrict__ gx,   // [B, T, E]
    const float* __restrict__ ga,   // [B, T, E]
    const float* __restrict__ h0,   // [1, E]
    float* __restrict__ out)        // [B, E]
{
    __shared__ __align__(16) float sw[360];          // h-side matrices, stride 12
    __shared__ __align__(16) float sx[2][EB * RS];   // [buf][row][10]
    __shared__ __align__(16) float sa[2][EB * RS];

    const int tid  = threadIdx.x;
    const int low  = tid & 15;        // element id within block
    const int grp  = tid >> 4;        // 0: owns j 0..4, 1: owns j 5..9
    const bool is0 = (grp == 0);
    const int b0   = blockIdx.x * EB;

    const uint32_t sxa = (uint32_t)__cvta_generic_to_shared(&sx[0][0]);
    const uint32_t saa = (uint32_t)__cvta_generic_to_shared(&sa[0][0]);
    const char* gxb = (const char*)gx + (size_t)b0 * (ROWB * 4);
    const char* gab = (const char*)ga + (size_t)b0 * (ROWB * 4);

    // stage timestep t into buffer d: each thread copies its own row (tid)
    auto stage = [&](int t, int d) {
        const int tb = t * (RS * 4);
        const uint32_t sbase = (uint32_t)((d * (EB * RS) + tid * RS) * 4);
        const size_t gbase = (size_t)tid * (ROWB * 4) + tb;
        #pragma unroll
        for (int c = 0; c < 5; c++) {
            cpa8(sxa + sbase + c * 8, gxb + gbase + c * 8);
            cpa8(saa + sbase + c * 8, gab + gbase + c * 8);
        }
        asm volatile("cp.async.commit_group;");
    };

    stage(0, 0);

    for (int i = tid; i < 360; i += NB) sw[i] = g_w2[400 + i];

    // owned-row weight bases (divergent between half-warps; 2-way at most)
    const int jb = grp * 5;           // first owned j
    const float* cwr = c_w + 0   + jb * 12;
    const float* cwz = c_w + 120 + jb * 12;
    const float* cwh = c_w + 240 + jb * 12;
    const float* swr = sw  + 0   + jb * 12;
    const float* swz = sw  + 120 + jb * 12;
    const float* swh = sw  + 240 + jb * 12;

    // state: hown = owned features (scalars), hp = full packed h (both units)
    float  hown[2][5];
    float2 hp[2][5];
    #pragma unroll
    for (int jj = 0; jj < 5; jj++) {
        float v = h0[jb + jj];
        hown[0][jj] = v; hown[1][jj] = v;
    }
    #pragma unroll
    for (int i = 0; i < 5; i++) {
        float2 v = make_float2(h0[2 * i], h0[2 * i + 1]);
        hp[0][i] = v; hp[1][i] = v;
    }

    __syncwarp();

    #pragma unroll 1
    for (int t = 0; t < T_; t++) {
        const int d = t & 1;
        if (t + 1 < T_) {
            stage(t + 1, d ^ 1);
            asm volatile("cp.async.wait_group 1;");
        } else {
            asm volatile("cp.async.wait_group 0;");
        }
        __syncwarp();

        const float* __restrict__ xb = &sx[d][0];
        const float* __restrict__ ab = &sa[d][0];

        // x features for both elements (rows low, low+16), naturally packed
        float2 xp[2][5];
        #pragma unroll
        for (int u = 0; u < 2; u++) {
            const float* xr = xb + (low + 16 * u) * RS;
            #pragma unroll
            for (int i = 0; i < 5; i++)
                xp[u][i] = *reinterpret_cast<const float2*>(xr + 2 * i);
        }

        // ---- loop 1: rp, zp for owned j ----
        float rp[2][5], zp[2][5];
        #pragma unroll
        for (int jj = 0; jj < 5; jj++) {
            W10 wxr = ldrow(cwr + jj * 12);
            W10 whr = ldrow(swr + jj * 12);
            W10 wxz = ldrow(cwz + jj * 12);
            W10 whz = ldrow(swz + jj * 12);
            float br = c_w[360 + jb + jj], bz = c_w[370 + jb + jj];
            #pragma unroll
            for (int u = 0; u < 2; u++) {
                float2 r = make_float2(br, 0.f);
                float2 z = make_float2(bz, 0.f);
                r = dotw(wxr, xp[u], r);
                r = dotw(whr, hp[u], r);
                z = dotw(wxz, xp[u], z);
                z = dotw(whz, hp[u], z);
                rp[u][jj] = r.x + r.y;
                zp[u][jj] = z.x + z.y;
            }
        }

        // ---- loop 2: hz for owned j, then exchange to full packed ----
        float hzo[2][5];
        #pragma unroll
        for (int u = 0; u < 2; u++)
            #pragma unroll
            for (int jj = 0; jj < 5; jj++)
                hzo[u][jj] = hown[u][jj] * sigf(zp[u][jj]);

        float2 hzp[2][5];
        exch5(hzo[0], is0, hzp[0]);
        exch5(hzo[1], is0, hzp[1]);

        // ---- loop 3: candidate pre-activation for owned j ----
        float hcp[2][5];
        #pragma unroll
        for (int jj = 0; jj < 5; jj++) {
            W10 wxh = ldrow(cwh + jj * 12);
            W10 whh = ldrow(swh + jj * 12);
            float bh = c_w[380 + jb + jj];
            #pragma unroll
            for (int u = 0; u < 2; u++) {
                float2 c = make_float2(bh, 0.f);
                c = dotw(wxh, xp[u], c);
                c = dotw(whh, hzp[u], c);
                hcp[u][jj] = c.x + c.y;
            }
        }

        // ---- loop 4: blend for owned j ----
        #pragma unroll
        for (int u = 0; u < 2; u++) {
            const float* ar = ab + (low + 16 * u) * RS + jb;
            #pragma unroll
            for (int jj = 0; jj < 5; jj++) {
                float av = ar[jj];
                float Ra = av * sigf(rp[u][jj]);
                float hc = tanh_ap(hcp[u][jj]);
                hown[u][jj] = fmaf(Ra, hc - hown[u][jj], hown[u][jj]);
            }
        }

        // ---- exchange h halves -> full packed for next step / output ----
        exch5(hown[0], is0, hp[0]);
        exch5(hown[1], is0, hp[1]);

        __syncwarp();
    }

    // write out: grp0 lane writes element low (u=0), grp1 writes low+16 (u=1)
    {
        const int row = b0 + low + 16 * grp;
        float2* p = reinterpret_cast<float2*>(out) + (size_t)row * 5;
        #pragma unroll
        for (int i = 0; i < 5; i++) p[i] = hp[grp][i];
    }
}

extern "C" void kernel_launch(void* const* d_in, const int* in_sizes, int n_in,
                              void* d_out, int out_size) {
    const float* gx   = (const float*)d_in[0];
    const float* ga   = (const float*)d_in[1];
    const float* h0   = (const float*)d_in[2];
    const float* Wi_r = (const float*)d_in[3];
    const float* bi_r = (const float*)d_in[4];
    const float* Wh_r = (const float*)d_in[5];
    const float* Ws_r = (const float*)d_in[6];
    const float* bs_r = (const float*)d_in[7];
    const float* Wi_z = (const float*)d_in[8];
    const float* bi_z = (const float*)d_in[9];
    const float* Wh_z = (const float*)d_in[10];
    const float* Ws_z = (const float*)d_in[11];
    const float* bs_z = (const float*)d_in[12];
    const float* Wi_h = (const float*)d_in[13];
    const float* bi_h = (const float*)d_in[14];
    const float* Wh_h = (const float*)d_in[15];
    const float* Wt_h = (const float*)d_in[16];
    const float* bt_h = (const float*)d_in[17];
    float* out = (float*)d_out;

    augru_precompute<<<1, 640>>>(Wi_r, bi_r, Wh_r, Ws_r, bs_r,
                                 Wi_z, bi_z, Wh_z, Ws_z, bs_z,
                                 Wi_h, bi_h, Wh_h, Wt_h, bt_h);

    void* g_ptr = nullptr;
    cudaGetSymbolAddress(&g_ptr, g_w2);
    cudaMemcpyToSymbolAsync(c_w, g_ptr, 390 * sizeof(float), 0,
                            cudaMemcpyDeviceToDevice, 0);

    augru_main<<<B_ / EB, NB>>>(gx, ga, h0, out);
}